// round 10
// baseline (speedup 1.0000x reference)
#include <cuda_runtime.h>
#include <cstdint>

// Problem constants: B=8, S=2048, D=256
static constexpr int Bn = 8;
static constexpr int Sn = 2048;
static constexpr int Dn = 256;
static constexpr int MROWS = Bn * Sn;   // 16384

// k-dim permutation within each 8-col group: q -> ((q&3)<<1)|(q>>2)
__host__ __device__ __forceinline__ int pidx(int c) {
    return (c & ~7) | (((c & 3) << 1) | ((c >> 2) & 1));
}

// ---------------- device scratch (no cudaMalloc allowed) ----------------
__device__ __align__(16) float g_P[MROWS * Dn];      // head @ U, tf32-rounded, k-permuted
__device__ __align__(16) float g_depR[MROWS * Dn];   // dep,  tf32-rounded, k-permuted
__device__ __align__(16) float g_UT[Dn * Dn];        // U^T,  tf32-rounded, k-permuted
__device__ float g_hs[MROWS];
__device__ float g_ds[MROWS];

// dependency flags (reset each launch by reset_flags)
__device__ unsigned g_fUT;          // -> 16
__device__ unsigned g_fP[128];      // -> 2 each (stage-1 tiles)
__device__ unsigned g_fRow[256];    // -> 16 each (128-row groups: 0-127 head, 128-255 dep)

__device__ __forceinline__ float rnd_tf32(float x) {
    uint32_t r; asm("cvt.rna.tf32.f32 %0, %1;" : "=r"(r) : "f"(x));
    return __uint_as_float(r);
}
__device__ __forceinline__ uint32_t f2tf(float x) {
    uint32_t r; asm("cvt.rna.tf32.f32 %0, %1;" : "=r"(r) : "f"(x));
    return r;
}
__device__ __forceinline__ void spin_until(volatile unsigned* f, unsigned v) {
    while (*f < v) __nanosleep(64);
}

__global__ void reset_flags() {
    int t = threadIdx.x;
    if (t == 0) g_fUT = 0;
    if (t < 128) g_fP[t] = 0;
    if (t < 256) g_fRow[t] = 0;
}

// ---------------- GEMM config: CTA 128x128, 4 warps, warp tile 64x64 ----------------
static constexpr int BM = 128, BN = 128, BK = 32, TH = 128;
static constexpr int STAGES = 3;
static constexpr int ATILE_F = BM * BK;
static constexpr int BTILE_F = BN * BK;
static constexpr uint32_t STAGE_BYTES = (ATILE_F + BTILE_F) * 4;      // 32768
static constexpr uint32_t EXTRA_OFF = STAGES * STAGE_BYTES;           // 98304
static constexpr uint32_t SMEM_BYTES = EXTRA_OFF + 1024;

// fused-grid layout
static constexpr int UT_BLKS = 16;
static constexpr int S1_BLKS = 256;     // (128 x-tiles) x (2 y-tiles)
static constexpr int PREP_BLKS = 4096;  // 8 rows each
static constexpr int S2_BLKS = 2048;    // 16 x 16 x 8
static constexpr int S1_OFF = UT_BLKS;
static constexpr int PREP_OFF = S1_OFF + S1_BLKS;
static constexpr int S2_OFF = PREP_OFF + PREP_BLKS;
static constexpr int TOTAL_BLKS = S2_OFF + S2_BLKS;

__device__ __forceinline__ uint32_t smem_u32(const void* p) {
    uint32_t a;
    asm("{ .reg .u64 t; cvta.to.shared.u64 t, %1; cvt.u32.u64 %0, t; }"
        : "=r"(a) : "l"(p));
    return a;
}
__device__ __forceinline__ void cpasync16(uint32_t dst, const float* src) {
    size_t g = __cvta_generic_to_global(src);
    asm volatile("cp.async.cg.shared.global [%0], [%1], 16;" :: "r"(dst), "l"(g));
}
__device__ __forceinline__ void mma_tf32(float* c, const uint32_t* a, const uint32_t* b) {
    asm volatile(
        "mma.sync.aligned.m16n8k8.row.col.f32.tf32.tf32.f32 "
        "{%0,%1,%2,%3}, {%4,%5,%6,%7}, {%8,%9}, {%0,%1,%2,%3};"
        : "+f"(c[0]), "+f"(c[1]), "+f"(c[2]), "+f"(c[3])
        : "r"(a[0]), "r"(a[1]), "r"(a[2]), "r"(a[3]), "r"(b[0]), "r"(b[1]));
}

// MODE 0: P = round(head) @ UT  (A raw + in-reg CVT). MODE 1: out = P@depR^T + hs+ds+b
template <int MODE>
__device__ __forceinline__ void gemm_body(float* sm, int x, int y, int z,
                                          float* __restrict__ out,
                                          const float* __restrict__ eb,
                                          const float* __restrict__ head,
                                          int tid) {
    const uint32_t sb = smem_u32(sm);
    const int w = tid >> 5, lane = tid & 31;
    const int wm = w >> 1, wn = w & 1;

    const float *Ag, *Bg;
    size_t aRow0, bRow0;
    if (MODE == 0) { Ag = head; Bg = g_UT;   aRow0 = (size_t)x * BM; bRow0 = (size_t)y * BN; }
    else           { Ag = g_P;  Bg = g_depR; aRow0 = (size_t)z * Sn + (size_t)x * BM;
                                              bRow0 = (size_t)z * Sn + (size_t)y * BN; }

    if (MODE == 1) {
        float* sex = sm + EXTRA_OFF / 4;
        sex[tid]       = g_hs[aRow0 + tid];
        sex[128 + tid] = g_ds[bRow0 + tid];
    }

    auto load_chunk = [&](int kt) {
        int stg = kt % STAGES;
        uint32_t baseA = sb + (uint32_t)stg * STAGE_BYTES;
        uint32_t baseB = baseA + ATILE_F * 4;
        int k0 = kt * BK;
        #pragma unroll
        for (int i = 0; i < 8; i++) {
            int cid = i * 128 + tid;
            int r = cid >> 3, c4 = cid & 7;
            uint32_t soff = (uint32_t)(r * 128 + (((2 * c4) ^ ((r & 3) << 2)) << 3));
            cpasync16(baseA + soff, Ag + (aRow0 + r) * Dn + k0 + c4 * 4);
        }
        #pragma unroll
        for (int i = 0; i < 8; i++) {
            int cid = i * 128 + tid;
            int r = cid >> 3, c4 = cid & 7;
            uint32_t soff = (uint32_t)(r * 128 + (((2 * c4) ^ ((r & 3) << 2)) << 3));
            cpasync16(baseB + soff, Bg + (bRow0 + r) * Dn + k0 + c4 * 4);
        }
        asm volatile("cp.async.commit_group;" ::: "memory");
    };

    float acc[4][8][4];
    #pragma unroll
    for (int i = 0; i < 4; i++)
        #pragma unroll
        for (int j = 0; j < 8; j++)
            #pragma unroll
            for (int t = 0; t < 4; t++) acc[i][j][t] = 0.f;

    load_chunk(0);
    load_chunk(1);

    const int rA = wm * 64 + (lane >> 2);
    const int rB = wn * 64 + (lane >> 2);
    const int kq = lane & 3;
    const uint32_t sw = ((uint32_t)((lane >> 2) & 3)) << 2;

    #pragma unroll 1
    for (int kt = 0; kt < 8; kt++) {
        if (kt == 7) { asm volatile("cp.async.wait_group 0;" ::: "memory"); }
        else         { asm volatile("cp.async.wait_group 1;" ::: "memory"); }
        __syncthreads();
        if (kt + 2 < 8) load_chunk(kt + 2);

        int stg = kt % STAGES;
        uint32_t baseA = sb + (uint32_t)stg * STAGE_BYTES;
        uint32_t baseB = baseA + ATILE_F * 4;

        #pragma unroll
        for (int ks = 0; ks < 4; ks++) {
            uint32_t a[4][4];
            if (MODE == 0) {
                uint32_t off0 = ((((uint32_t)(4 * ks)) ^ sw) << 3) + kq * 4;
                uint32_t off2 = ((((uint32_t)(4 * ks + 2)) ^ sw) << 3) + kq * 4;
                #pragma unroll
                for (int i = 0; i < 4; i++) {
                    uint32_t rb = baseA + (uint32_t)(rA + i * 16) * 128;
                    float x0, x1, x2, x3;
                    asm volatile("ld.shared.f32 %0, [%1];" : "=f"(x0) : "r"(rb + off0));
                    asm volatile("ld.shared.f32 %0, [%1];" : "=f"(x1) : "r"(rb + 1024 + off0));
                    asm volatile("ld.shared.f32 %0, [%1];" : "=f"(x2) : "r"(rb + off2));
                    asm volatile("ld.shared.f32 %0, [%1];" : "=f"(x3) : "r"(rb + 1024 + off2));
                    a[i][0] = f2tf(x0); a[i][1] = f2tf(x1);
                    a[i][2] = f2tf(x2); a[i][3] = f2tf(x3);
                }
            } else {
                uint32_t slotOff = (((uint32_t)(ks * 4 + kq)) ^ sw) << 3;
                #pragma unroll
                for (int i = 0; i < 4; i++) {
                    uint32_t ad0 = baseA + (uint32_t)(rA + i * 16) * 128 + slotOff;
                    float2 f0, f1;
                    asm volatile("ld.shared.v2.f32 {%0,%1}, [%2];"
                                 : "=f"(f0.x), "=f"(f0.y) : "r"(ad0));
                    asm volatile("ld.shared.v2.f32 {%0,%1}, [%2];"
                                 : "=f"(f1.x), "=f"(f1.y) : "r"(ad0 + 8 * 128));
                    a[i][0] = __float_as_uint(f0.x);
                    a[i][2] = __float_as_uint(f0.y);
                    a[i][1] = __float_as_uint(f1.x);
                    a[i][3] = __float_as_uint(f1.y);
                }
            }
            uint32_t slotOffB = (((uint32_t)(ks * 4 + kq)) ^ sw) << 3;
            uint32_t b[8][2];
            #pragma unroll
            for (int j = 0; j < 8; j++) {
                uint32_t bd = baseB + (uint32_t)(rB + j * 8) * 128 + slotOffB;
                float2 f;
                asm volatile("ld.shared.v2.f32 {%0,%1}, [%2];"
                             : "=f"(f.x), "=f"(f.y) : "r"(bd));
                b[j][0] = __float_as_uint(f.x);
                b[j][1] = __float_as_uint(f.y);
            }
            #pragma unroll
            for (int i = 0; i < 4; i++)
                #pragma unroll
                for (int j = 0; j < 8; j++)
                    mma_tf32(acc[i][j], a[i], b[j]);
        }
    }

    if (MODE == 0) {
        size_t col0 = (size_t)y * BN;
        #pragma unroll
        for (int i = 0; i < 4; i++) {
            size_t gr = (aRow0 + wm * 64 + i * 16 + (lane >> 2)) * (size_t)Dn + col0;
            #pragma unroll
            for (int j = 0; j < 8; j++) {
                int c = wn * 64 + j * 8 + (lane & 3) * 2;
                int p0 = pidx(c), p1 = pidx(c + 1);
                g_P[gr + p0]          = rnd_tf32(acc[i][j][0]);
                g_P[gr + p1]          = rnd_tf32(acc[i][j][1]);
                g_P[gr + 8 * Dn + p0] = rnd_tf32(acc[i][j][2]);
                g_P[gr + 8 * Dn + p1] = rnd_tf32(acc[i][j][3]);
            }
        }
    } else {
        float bias = __ldg(eb);
        const float* shs = sm + EXTRA_OFF / 4;
        const float* sds = shs + 128;
        #pragma unroll
        for (int i = 0; i < 4; i++) {
            int rl = wm * 64 + i * 16 + (lane >> 2);
            float hs0 = shs[rl] + bias;
            float hs1 = shs[rl + 8] + bias;
            size_t gr0 = (aRow0 + rl) * (size_t)Sn + (size_t)y * BN;
            #pragma unroll
            for (int j = 0; j < 8; j++) {
                int c = wn * 64 + j * 8 + (lane & 3) * 2;
                float d0 = sds[c], d1 = sds[c + 1];
                *(float2*)(out + gr0 + c) =
                    make_float2(acc[i][j][0] + hs0 + d0, acc[i][j][1] + hs0 + d1);
                *(float2*)(out + gr0 + 8 * (size_t)Sn + c) =
                    make_float2(acc[i][j][2] + hs1 + d0, acc[i][j][3] + hs1 + d1);
            }
        }
    }
}

// ---------------- fused kernel: UT | stage-1 | row-prep | stage-2 ----------------
__global__ void __launch_bounds__(TH, 2)
fused_kernel(float* __restrict__ out, const float* __restrict__ eb,
             const float* __restrict__ head, const float* __restrict__ dep,
             const float* __restrict__ U, const float* __restrict__ Wv) {
    extern __shared__ float sm[];
    const int bid = blockIdx.x;
    const int tid = threadIdx.x;
    const int w = tid >> 5, lane = tid & 31;

    if (bid < UT_BLKS) {
        // ---- UT: UT[e, pidx(d)] = round(U[d, e]) via 64x64 smem transpose ----
        float (*tile)[65] = (float(*)[65])sm;
        int d0 = (bid & 3) * 64, e0 = (bid >> 2) * 64;
        #pragma unroll
        for (int i = 0; i < 32; i++) {
            int ii = i * 128 + tid;
            int r = ii >> 6, c = ii & 63;
            tile[r][c] = rnd_tf32(U[(size_t)(d0 + r) * Dn + e0 + c]);
        }
        __syncthreads();
        #pragma unroll
        for (int i = 0; i < 32; i++) {
            int ii = i * 128 + tid;
            int r = ii >> 6, c = ii & 63;
            g_UT[(size_t)(e0 + r) * Dn + pidx(d0 + c)] = tile[c][r];
        }
        __syncthreads();
        if (tid == 0) { __threadfence(); atomicAdd(&g_fUT, 1u); }
        return;
    }

    if (bid < PREP_OFF) {
        // ---- stage-1 GEMM: wait for UT, then P tile ----
        int sbid = bid - S1_OFF;
        int x = sbid & 127, y = sbid >> 7;
        if (tid == 0) spin_until(&g_fUT, UT_BLKS);
        __syncthreads();
        gemm_body<0>(sm, x, y, 0, out, eb, head, tid);
        __syncthreads();
        if (tid == 0) { __threadfence(); atomicAdd(&g_fP[x], 1u); }
        return;
    }

    if (bid < S2_OFF) {
        // ---- row prep: 8 rows/block, 2 rows/warp; coalesced permuted writes ----
        int idx0 = (bid - PREP_OFF) * 8;
        bool isHead = idx0 < MROWS;
        const float* src = isHead ? head : dep;
        const float* wvp = isHead ? Wv : (Wv + Dn);
        int base = isHead ? idx0 : idx0 - MROWS;
        float4 w0 = *(const float4*)(wvp + lane * 8);
        float4 w1 = *(const float4*)(wvp + lane * 8 + 4);
        #pragma unroll
        for (int rit = 0; rit < 2; rit++) {
            int rr = base + w * 2 + rit;
            const float* sp = src + (size_t)rr * Dn + lane * 8;
            float4 a0 = *(const float4*)sp;
            float4 a1 = *(const float4*)(sp + 4);
            float p = a0.x * w0.x + a0.y * w0.y + a0.z * w0.z + a0.w * w0.w
                    + a1.x * w1.x + a1.y * w1.y + a1.z * w1.z + a1.w * w1.w;
            #pragma unroll
            for (int o = 16; o; o >>= 1) p += __shfl_down_sync(0xFFFFFFFFu, p, o);
            if (lane == 0) { if (isHead) g_hs[rr] = p; else g_ds[rr] = p; }
            if (!isHead) {
                float* db = g_depR + (size_t)rr * Dn + lane * 8;
                // permuted within group: [a0.x,a1.x,a0.y,a1.y] [a0.z,a1.z,a0.w,a1.w]
                *(float4*)db = make_float4(rnd_tf32(a0.x), rnd_tf32(a1.x),
                                           rnd_tf32(a0.y), rnd_tf32(a1.y));
                *(float4*)(db + 4) = make_float4(rnd_tf32(a0.z), rnd_tf32(a1.z),
                                                 rnd_tf32(a0.w), rnd_tf32(a1.w));
            }
        }
        __syncthreads();
        if (tid == 0) {
            __threadfence();
            int grp = isHead ? (idx0 >> 7) : (128 + ((idx0 - MROWS) >> 7));
            atomicAdd(&g_fRow[grp], 1u);
        }
        return;
    }

    // ---- stage-2 GEMM: wait for P tile + hs group + ds/depR group ----
    {
        int sbid = bid - S2_OFF;
        int x = sbid & 15, y = (sbid >> 4) & 15, z = sbid >> 8;
        int t = z * 16 + x;
        if (tid == 0) {
            spin_until(&g_fP[t], 2u);
            spin_until(&g_fRow[t], 16u);                 // hs rows (head group)
            spin_until(&g_fRow[128 + z * 16 + y], 16u);  // ds + depR rows (dep group)
        }
        __syncthreads();
        gemm_body<1>(sm, x, y, z, out, eb, head, tid);
    }
}

// ---------------- kernel_launch ----------------
extern "C" void kernel_launch(void* const* d_in, const int* in_sizes, int n_in,
                              void* d_out, int out_size) {
    const float* head = (const float*)d_in[0];
    const float* dep  = (const float*)d_in[1];
    const float* U    = (const float*)d_in[2];
    const float* W    = (const float*)d_in[3];
    const float* eb   = (const float*)d_in[4];
    float* out = (float*)d_out;
    (void)in_sizes; (void)n_in; (void)out_size;

    cudaFuncSetAttribute(fused_kernel,
                         cudaFuncAttributeMaxDynamicSharedMemorySize, SMEM_BYTES);

    reset_flags<<<1, 256>>>();
    fused_kernel<<<TOTAL_BLKS, TH, SMEM_BYTES>>>(out, eb, head, dep, U, W);
}

// round 11
// speedup vs baseline: 1.1358x; 1.1358x over previous
#include <cuda_runtime.h>
#include <cstdint>

// Problem constants: B=8, S=2048, D=256
static constexpr int Bn = 8;
static constexpr int Sn = 2048;
static constexpr int Dn = 256;
static constexpr int MROWS = Bn * Sn;   // 16384

// k-dim permutation within each 8-col group: q -> ((q&3)<<1)|(q>>2)
__host__ __device__ __forceinline__ int pidx(int c) {
    return (c & ~7) | (((c & 3) << 1) | ((c >> 2) & 1));
}

// ---------------- device scratch (no cudaMalloc allowed) ----------------
__device__ __align__(16) float g_P[MROWS * Dn];      // head @ U, tf32-rounded, k-permuted
__device__ __align__(16) float g_depR[MROWS * Dn];   // dep,  tf32-rounded, k-permuted
__device__ __align__(16) float g_UT[Dn * Dn];        // U^T,  tf32-rounded, k-permuted
__device__ float g_hs[MROWS];
__device__ float g_ds[MROWS];

__device__ __forceinline__ float rnd_tf32(float x) {
    uint32_t r; asm("cvt.rna.tf32.f32 %0, %1;" : "=r"(r) : "f"(x));
    return __uint_as_float(r);
}
__device__ __forceinline__ uint32_t f2tf(float x) {
    uint32_t r; asm("cvt.rna.tf32.f32 %0, %1;" : "=r"(r) : "f"(x));
    return r;
}

// ---------------- prep: rows (hs/ds/depR) + UT tile-transpose; NO dynamic smem ----------------
// 16 rows/block (2 rows/warp, 8 warps of the 256-thread block... we use 256 thr = 8 warps)
static constexpr int ROW_BLOCKS = (2 * MROWS) / 16;   // 2048
static constexpr int UT_BLOCKS = 16;                  // 64x64 tiles of U

__global__ void __launch_bounds__(256) prep_all(const float* __restrict__ head,
                                                const float* __restrict__ dep,
                                                const float* __restrict__ U,
                                                const float* __restrict__ W) {
    __shared__ float tile[64][65];
    int bid = blockIdx.x;
    int tid = threadIdx.x, w = tid >> 5, lane = tid & 31;

    if (bid < ROW_BLOCKS) {
        int idx0 = bid * 16;                    // block handles rows idx0..idx0+15
        bool isHead = idx0 < MROWS;             // blocks never straddle (MROWS%16==0)
        const float* src = isHead ? head : dep;
        const float* wvp = isHead ? W : (W + Dn);
        int base = isHead ? idx0 : idx0 - MROWS;
        float4 w0 = *(const float4*)(wvp + lane * 8);
        float4 w1 = *(const float4*)(wvp + lane * 8 + 4);
        #pragma unroll
        for (int rit = 0; rit < 2; rit++) {
            int rr = base + w * 2 + rit;
            const float* sp = src + (size_t)rr * Dn + lane * 8;
            float4 a0 = *(const float4*)sp;
            float4 a1 = *(const float4*)(sp + 4);
            float p = a0.x * w0.x + a0.y * w0.y + a0.z * w0.z + a0.w * w0.w
                    + a1.x * w1.x + a1.y * w1.y + a1.z * w1.z + a1.w * w1.w;
            #pragma unroll
            for (int o = 16; o; o >>= 1) p += __shfl_down_sync(0xFFFFFFFFu, p, o);
            if (lane == 0) { if (isHead) g_hs[rr] = p; else g_ds[rr] = p; }
            if (!isHead) {
                // coalesced permuted write: pidx maps group [c0..c7] ->
                // [a0.x,a1.x,a0.y,a1.y, a0.z,a1.z,a0.w,a1.w]
                float* db = g_depR + (size_t)rr * Dn + lane * 8;
                *(float4*)db = make_float4(rnd_tf32(a0.x), rnd_tf32(a1.x),
                                           rnd_tf32(a0.y), rnd_tf32(a1.y));
                *(float4*)(db + 4) = make_float4(rnd_tf32(a0.z), rnd_tf32(a1.z),
                                                 rnd_tf32(a0.w), rnd_tf32(a1.w));
            }
        }
    } else {
        // UT[e, pidx(d)] = round(U[d, e]) via 64x64 smem transpose
        int tb = bid - ROW_BLOCKS;              // 0..15
        int d0 = (tb & 3) * 64, e0 = (tb >> 2) * 64;
        #pragma unroll
        for (int i = 0; i < 16; i++) {
            int ii = i * 256 + tid;
            int r = ii >> 6, c = ii & 63;
            tile[r][c] = rnd_tf32(U[(size_t)(d0 + r) * Dn + e0 + c]);
        }
        __syncthreads();
        #pragma unroll
        for (int i = 0; i < 16; i++) {
            int ii = i * 256 + tid;
            int r = ii >> 6, c = ii & 63;
            g_UT[(size_t)(e0 + r) * Dn + pidx(d0 + c)] = tile[c][r];
        }
    }
}

// ---------------- tf32 MMA GEMM: CTA tile 128x128, 4 warps, warp tile 64x64 ----------------
static constexpr int BM = 128, BN = 128, BK = 32, TH = 128;
static constexpr int STAGES = 3;
static constexpr int ATILE_F = BM * BK;
static constexpr int BTILE_F = BN * BK;
static constexpr uint32_t STAGE_BYTES = (ATILE_F + BTILE_F) * 4;      // 32768
static constexpr uint32_t EXTRA_OFF = STAGES * STAGE_BYTES;           // 98304
static constexpr uint32_t SMEM_BYTES = EXTRA_OFF + 1024;

__device__ __forceinline__ uint32_t smem_u32(const void* p) {
    uint32_t a;
    asm("{ .reg .u64 t; cvta.to.shared.u64 t, %1; cvt.u32.u64 %0, t; }"
        : "=r"(a) : "l"(p));
    return a;
}
__device__ __forceinline__ void cpasync16(uint32_t dst, const float* src) {
    size_t g = __cvta_generic_to_global(src);
    asm volatile("cp.async.cg.shared.global [%0], [%1], 16;" :: "r"(dst), "l"(g));
}
__device__ __forceinline__ void mma_tf32(float* c, const uint32_t* a, const uint32_t* b) {
    asm volatile(
        "mma.sync.aligned.m16n8k8.row.col.f32.tf32.tf32.f32 "
        "{%0,%1,%2,%3}, {%4,%5,%6,%7}, {%8,%9}, {%0,%1,%2,%3};"
        : "+f"(c[0]), "+f"(c[1]), "+f"(c[2]), "+f"(c[3])
        : "r"(a[0]), "r"(a[1]), "r"(a[2]), "r"(a[3]), "r"(b[0]), "r"(b[1]));
}

// MODE 0: grid (128,2,1): P = round(head) @ UT  (A raw + in-reg CVT)
// MODE 1: grid (16,16,8): out[b] = P[b] @ depR[b]^T + hs + ds + bias
template <int MODE>
__global__ void __launch_bounds__(TH, 2)
gemm_kernel(float* __restrict__ out, const float* __restrict__ eb,
            const float* __restrict__ head) {
    extern __shared__ float sm[];
    const uint32_t sb = smem_u32(sm);

    const int tid = threadIdx.x;
    const int w = tid >> 5, lane = tid & 31;
    const int wm = w >> 1;
    const int wn = w & 1;
    const int x = blockIdx.x, y = blockIdx.y, z = blockIdx.z;

    const float *Ag, *Bg;
    size_t aRow0, bRow0;
    if (MODE == 0) { Ag = head;  Bg = g_UT;   aRow0 = (size_t)x * BM; bRow0 = (size_t)y * BN; }
    else           { Ag = g_P;   Bg = g_depR; aRow0 = (size_t)z * Sn + (size_t)x * BM;
                                               bRow0 = (size_t)z * Sn + (size_t)y * BN; }

    if (MODE == 1) {
        float* sex = sm + EXTRA_OFF / 4;
        sex[tid]       = g_hs[aRow0 + tid];
        sex[128 + tid] = g_ds[bRow0 + tid];
    }

    auto load_chunk = [&](int kt) {
        int stg = kt % STAGES;
        uint32_t baseA = sb + (uint32_t)stg * STAGE_BYTES;
        uint32_t baseB = baseA + ATILE_F * 4;
        int k0 = kt * BK;
        #pragma unroll
        for (int i = 0; i < 8; i++) {
            int cid = i * 128 + tid;
            int r = cid >> 3, c4 = cid & 7;
            uint32_t soff = (uint32_t)(r * 128 + (((2 * c4) ^ ((r & 3) << 2)) << 3));
            cpasync16(baseA + soff, Ag + (aRow0 + r) * Dn + k0 + c4 * 4);
        }
        #pragma unroll
        for (int i = 0; i < 8; i++) {
            int cid = i * 128 + tid;
            int r = cid >> 3, c4 = cid & 7;
            uint32_t soff = (uint32_t)(r * 128 + (((2 * c4) ^ ((r & 3) << 2)) << 3));
            cpasync16(baseB + soff, Bg + (bRow0 + r) * Dn + k0 + c4 * 4);
        }
        asm volatile("cp.async.commit_group;" ::: "memory");
    };

    float acc[4][8][4];
    #pragma unroll
    for (int i = 0; i < 4; i++)
        #pragma unroll
        for (int j = 0; j < 8; j++)
            #pragma unroll
            for (int t = 0; t < 4; t++) acc[i][j][t] = 0.f;

    load_chunk(0);
    load_chunk(1);

    const int rA = wm * 64 + (lane >> 2);
    const int rB = wn * 64 + (lane >> 2);
    const int kq = lane & 3;
    const uint32_t sw = ((uint32_t)((lane >> 2) & 3)) << 2;

    #pragma unroll 1
    for (int kt = 0; kt < 8; kt++) {
        if (kt == 7) { asm volatile("cp.async.wait_group 0;" ::: "memory"); }
        else         { asm volatile("cp.async.wait_group 1;" ::: "memory"); }
        __syncthreads();
        if (kt + 2 < 8) load_chunk(kt + 2);

        int stg = kt % STAGES;
        uint32_t baseA = sb + (uint32_t)stg * STAGE_BYTES;
        uint32_t baseB = baseA + ATILE_F * 4;

        #pragma unroll
        for (int ks = 0; ks < 4; ks++) {
            uint32_t a[4][4];
            if (MODE == 0) {
                uint32_t off0 = ((((uint32_t)(4 * ks)) ^ sw) << 3) + kq * 4;
                uint32_t off2 = ((((uint32_t)(4 * ks + 2)) ^ sw) << 3) + kq * 4;
                #pragma unroll
                for (int i = 0; i < 4; i++) {
                    uint32_t rb = baseA + (uint32_t)(rA + i * 16) * 128;
                    float x0, x1, x2, x3;
                    asm volatile("ld.shared.f32 %0, [%1];" : "=f"(x0) : "r"(rb + off0));
                    asm volatile("ld.shared.f32 %0, [%1];" : "=f"(x1) : "r"(rb + 1024 + off0));
                    asm volatile("ld.shared.f32 %0, [%1];" : "=f"(x2) : "r"(rb + off2));
                    asm volatile("ld.shared.f32 %0, [%1];" : "=f"(x3) : "r"(rb + 1024 + off2));
                    a[i][0] = f2tf(x0); a[i][1] = f2tf(x1);
                    a[i][2] = f2tf(x2); a[i][3] = f2tf(x3);
                }
            } else {
                uint32_t slotOff = (((uint32_t)(ks * 4 + kq)) ^ sw) << 3;
                #pragma unroll
                for (int i = 0; i < 4; i++) {
                    uint32_t ad0 = baseA + (uint32_t)(rA + i * 16) * 128 + slotOff;
                    float2 f0, f1;
                    asm volatile("ld.shared.v2.f32 {%0,%1}, [%2];"
                                 : "=f"(f0.x), "=f"(f0.y) : "r"(ad0));
                    asm volatile("ld.shared.v2.f32 {%0,%1}, [%2];"
                                 : "=f"(f1.x), "=f"(f1.y) : "r"(ad0 + 8 * 128));
                    a[i][0] = __float_as_uint(f0.x);
                    a[i][2] = __float_as_uint(f0.y);
                    a[i][1] = __float_as_uint(f1.x);
                    a[i][3] = __float_as_uint(f1.y);
                }
            }
            uint32_t slotOffB = (((uint32_t)(ks * 4 + kq)) ^ sw) << 3;
            uint32_t b[8][2];
            #pragma unroll
            for (int j = 0; j < 8; j++) {
                uint32_t bd = baseB + (uint32_t)(rB + j * 8) * 128 + slotOffB;
                float2 f;
                asm volatile("ld.shared.v2.f32 {%0,%1}, [%2];"
                             : "=f"(f.x), "=f"(f.y) : "r"(bd));
                b[j][0] = __float_as_uint(f.x);
                b[j][1] = __float_as_uint(f.y);
            }
            #pragma unroll
            for (int i = 0; i < 4; i++)
                #pragma unroll
                for (int j = 0; j < 8; j++)
                    mma_tf32(acc[i][j], a[i], b[j]);
        }
    }

    if (MODE == 0) {
        size_t col0 = (size_t)y * BN;
        #pragma unroll
        for (int i = 0; i < 4; i++) {
            size_t gr = (aRow0 + wm * 64 + i * 16 + (lane >> 2)) * (size_t)Dn + col0;
            #pragma unroll
            for (int j = 0; j < 8; j++) {
                int c = wn * 64 + j * 8 + (lane & 3) * 2;
                int p0 = pidx(c), p1 = pidx(c + 1);
                g_P[gr + p0]          = rnd_tf32(acc[i][j][0]);
                g_P[gr + p1]          = rnd_tf32(acc[i][j][1]);
                g_P[gr + 8 * Dn + p0] = rnd_tf32(acc[i][j][2]);
                g_P[gr + 8 * Dn + p1] = rnd_tf32(acc[i][j][3]);
            }
        }
    } else {
        float bias = __ldg(eb);
        const float* shs = sm + EXTRA_OFF / 4;
        const float* sds = shs + 128;
        #pragma unroll
        for (int i = 0; i < 4; i++) {
            int rl = wm * 64 + i * 16 + (lane >> 2);
            float hs0 = shs[rl] + bias;
            float hs1 = shs[rl + 8] + bias;
            size_t gr0 = (aRow0 + rl) * (size_t)Sn + (size_t)y * BN;
            #pragma unroll
            for (int j = 0; j < 8; j++) {
                int c = wn * 64 + j * 8 + (lane & 3) * 2;
                float d0 = sds[c], d1 = sds[c + 1];
                *(float2*)(out + gr0 + c) =
                    make_float2(acc[i][j][0] + hs0 + d0, acc[i][j][1] + hs0 + d1);
                *(float2*)(out + gr0 + 8 * (size_t)Sn + c) =
                    make_float2(acc[i][j][2] + hs1 + d0, acc[i][j][3] + hs1 + d1);
            }
        }
    }
}

// ---------------- kernel_launch ----------------
extern "C" void kernel_launch(void* const* d_in, const int* in_sizes, int n_in,
                              void* d_out, int out_size) {
    const float* head = (const float*)d_in[0];
    const float* dep  = (const float*)d_in[1];
    const float* U    = (const float*)d_in[2];
    const float* W    = (const float*)d_in[3];
    const float* eb   = (const float*)d_in[4];
    float* out = (float*)d_out;
    (void)in_sizes; (void)n_in; (void)out_size;

    cudaFuncSetAttribute(gemm_kernel<0>,
                         cudaFuncAttributeMaxDynamicSharedMemorySize, SMEM_BYTES);
    cudaFuncSetAttribute(gemm_kernel<1>,
                         cudaFuncAttributeMaxDynamicSharedMemorySize, SMEM_BYTES);

    // 1) prep: hs/ds/depR rows (coalesced permuted writes) + UT transpose
    prep_all<<<ROW_BLOCKS + UT_BLOCKS, 256>>>(head, dep, U, W);
    // 2) stage-1: P = round(head) @ UT
    gemm_kernel<0><<<dim3(BM, 2, 1), TH, SMEM_BYTES>>>(out, eb, head);
    // 3) stage-2: out[b] = P[b] @ depR[b]^T + hs + ds + bias
    gemm_kernel<1><<<dim3(Sn / BM, Sn / BN, Bn), TH, SMEM_BYTES>>>(out, eb, head);
}